// round 11
// baseline (speedup 1.0000x reference)
#include <cuda_runtime.h>
#include <math.h>
#include <stdint.h>

#define BB 32
#define SS 2048
#define KK 512
#define VV 512
#define HH 256
#define MT (SS*BB)      // 65536 rows (row = s*BB + b)
#define SCH 32          // s-chunks for weighted-sum split
#define SPER (SS/SCH)   // 64

// scratch (static device arrays — no allocation allowed)
__device__ float g_hq2[BB*HH];            // q@Wq + bq + bk, [b][h]
__device__ float g_logit[MT];             // logit[s*BB + b]
__device__ float g_partial[SCH*BB*VV];    // split-S partial weighted sums

__device__ __forceinline__ uint32_t f2tf32(float f) {
    uint32_t r;
    asm("cvt.rna.tf32.f32 %0, %1;" : "=r"(r) : "f"(f));
    return r;
}

#define MMA_TF32(d, a, b)                                                       \
    asm volatile("mma.sync.aligned.m16n8k8.row.col.f32.tf32.tf32.f32 "          \
                 "{%0,%1,%2,%3}, {%4,%5,%6,%7}, {%8,%9}, {%0,%1,%2,%3};"        \
                 : "+f"(d[0]), "+f"(d[1]), "+f"(d[2]), "+f"(d[3])               \
                 : "r"(a[0]), "r"(a[1]), "r"(a[2]), "r"(a[3]),                  \
                   "r"(b[0]), "r"(b[1]))

// ---------------------------------------------------------------------------
// Kernel 1: hq2[b][h] = q[b]·Wq[h] + bq[h] + bk[h]
// ---------------------------------------------------------------------------
__global__ void hq_kernel(const float* __restrict__ q, const float* __restrict__ Wq,
                          const float* __restrict__ bq, const float* __restrict__ bk) {
    int b = blockIdx.x;
    int h = threadIdx.x;  // 256 threads, one per h
    __shared__ float qs[KK];
    for (int i = threadIdx.x; i < KK; i += blockDim.x) qs[i] = q[b*KK + i];
    __syncthreads();
    const float* w = Wq + (size_t)h * KK;
    float acc = 0.f;
    #pragma unroll 8
    for (int kk = 0; kk < KK; kk++) acc += qs[kk] * w[kk];
    g_hq2[b*HH + h] = acc + bq[h] + bk[h];
}

// ---------------------------------------------------------------------------
// Kernel 2: tf32 tensor-core GEMM + tanh + Wo reduction -> logit[row]
// B smem uses XOR swizzle: phys(k,n) = k*256 + (n ^ (8*(k&3)))
//   -> fragment-load banks = 8*(t^const) + g : all 32 lanes distinct.
// Double-buffered, register prefetch, one __syncthreads per k-tile.
// CTA 512 thr (warp grid 4x4), tile 128x256, BK=16.
// ---------------------------------------------------------------------------
#define AS_STR 20
#define NK_TILES (KK/16)
#define LOGIT_SMEM ((2*128*AS_STR + 2*16*256)*4 + HH*4 + 128*4*4)

__global__ __launch_bounds__(512, 1) void logit_kernel(
    const float* __restrict__ kmat, const float* __restrict__ Wk,
    const float* __restrict__ Wo,   const float* __restrict__ bo) {
    extern __shared__ char smem_raw[];
    uint32_t* AsBuf[2];
    uint32_t* BsBuf[2];
    AsBuf[0] = (uint32_t*)smem_raw;
    AsBuf[1] = AsBuf[0] + 128*AS_STR;
    BsBuf[0] = AsBuf[1] + 128*AS_STR;
    BsBuf[1] = BsBuf[0] + 16*256;
    float* wos = (float*)(BsBuf[1] + 16*256);       // [HH]
    float* red = wos + HH;                           // [128][4]

    const int tid  = threadIdx.x;
    const int lane = tid & 31;
    const int warp = tid >> 5;
    const int wm   = warp >> 2;            // 0..3 (M)
    const int wn   = warp & 3;             // 0..3 (N)
    const int g    = lane >> 2;            // groupID
    const int t    = lane & 3;             // thread-in-group
    const int base = blockIdx.x * 128;

    if (tid < HH) wos[tid] = Wo[tid];

    // staging indices
    const int arow = tid >> 2;             // 0..127
    const int acol = (tid & 3) * 4;        // 0,4,8,12
    const int bh   = tid & 255;            // n (0..255)
    const int bko  = (tid >> 8) * 8;       // k rows 0..7 or 8..15

    float acc[2][8][4];
    #pragma unroll
    for (int mt = 0; mt < 2; mt++)
        #pragma unroll
        for (int nt = 0; nt < 8; nt++)
            #pragma unroll
            for (int c = 0; c < 4; c++) acc[mt][nt][c] = 0.f;

    const float* apt = kmat + (size_t)(base + arow)*KK + acol;
    const float* bpt = Wk + (size_t)bh*KK + bko;

    const int xort = t * 8;                // fragment-load XOR (rows kk+t, kk+t+4 share k&3==t)

    // ---- prologue: tile 0 -> regs -> smem buf 0 ----
    float4 av  = *(const float4*)(apt);
    float4 bv0 = *(const float4*)(bpt);
    float4 bv1 = *(const float4*)(bpt + 4);
    {
        uint32_t* As = AsBuf[0];
        uint32_t* Bs = BsBuf[0];
        uint4 at;
        at.x = f2tf32(av.x); at.y = f2tf32(av.y);
        at.z = f2tf32(av.z); at.w = f2tf32(av.w);
        *(uint4*)&As[arow*AS_STR + acol] = at;
        Bs[(bko+0)*256 + (bh ^  0)] = f2tf32(bv0.x);
        Bs[(bko+1)*256 + (bh ^  8)] = f2tf32(bv0.y);
        Bs[(bko+2)*256 + (bh ^ 16)] = f2tf32(bv0.z);
        Bs[(bko+3)*256 + (bh ^ 24)] = f2tf32(bv0.w);
        Bs[(bko+4)*256 + (bh ^  0)] = f2tf32(bv1.x);
        Bs[(bko+5)*256 + (bh ^  8)] = f2tf32(bv1.y);
        Bs[(bko+6)*256 + (bh ^ 16)] = f2tf32(bv1.z);
        Bs[(bko+7)*256 + (bh ^ 24)] = f2tf32(bv1.w);
    }
    __syncthreads();

    for (int it = 0; it < NK_TILES; it++) {
        // issue gmem loads for tile it+1 BEFORE compute (latency hidden by MMAs)
        if (it + 1 < NK_TILES) {
            int kn = (it + 1) * 16;
            av  = *(const float4*)(apt + kn);
            bv0 = *(const float4*)(bpt + kn);
            bv1 = *(const float4*)(bpt + kn + 4);
        }

        const uint32_t* As = AsBuf[it & 1];
        const uint32_t* Bs = BsBuf[it & 1];
        #pragma unroll
        for (int ks = 0; ks < 2; ks++) {
            const int kk = ks * 8;
            uint32_t afr[2][4];
            #pragma unroll
            for (int mt = 0; mt < 2; mt++) {
                int r = wm*32 + mt*16;
                afr[mt][0] = As[(r + g    )*AS_STR + kk + t    ];
                afr[mt][1] = As[(r + g + 8)*AS_STR + kk + t    ];
                afr[mt][2] = As[(r + g    )*AS_STR + kk + t + 4];
                afr[mt][3] = As[(r + g + 8)*AS_STR + kk + t + 4];
            }
            uint32_t bfr[8][2];
            #pragma unroll
            for (int nt = 0; nt < 8; nt++) {
                int n = wn*64 + nt*8 + g;
                bfr[nt][0] = Bs[(kk + t    )*256 + (n ^ xort)];
                bfr[nt][1] = Bs[(kk + t + 4)*256 + (n ^ xort)];
            }
            #pragma unroll
            for (int mt = 0; mt < 2; mt++)
                #pragma unroll
                for (int nt = 0; nt < 8; nt++)
                    MMA_TF32(acc[mt][nt], afr[mt], bfr[nt]);
        }

        // store prefetched tile into the other buffer
        if (it + 1 < NK_TILES) {
            uint32_t* Asn = AsBuf[(it + 1) & 1];
            uint32_t* Bsn = BsBuf[(it + 1) & 1];
            uint4 at;
            at.x = f2tf32(av.x); at.y = f2tf32(av.y);
            at.z = f2tf32(av.z); at.w = f2tf32(av.w);
            *(uint4*)&Asn[arow*AS_STR + acol] = at;
            Bsn[(bko+0)*256 + (bh ^  0)] = f2tf32(bv0.x);
            Bsn[(bko+1)*256 + (bh ^  8)] = f2tf32(bv0.y);
            Bsn[(bko+2)*256 + (bh ^ 16)] = f2tf32(bv0.z);
            Bsn[(bko+3)*256 + (bh ^ 24)] = f2tf32(bv0.w);
            Bsn[(bko+4)*256 + (bh ^  0)] = f2tf32(bv1.x);
            Bsn[(bko+5)*256 + (bh ^  8)] = f2tf32(bv1.y);
            Bsn[(bko+6)*256 + (bh ^ 16)] = f2tf32(bv1.z);
            Bsn[(bko+7)*256 + (bh ^ 24)] = f2tf32(bv1.w);
        }
        __syncthreads();
    }

    // epilogue: tanh + Wo-weighted reduce across H
    // C mapping: c0 -> (row g, col 2t), c1 -> (g, 2t+1), c2/c3 -> row g+8
    float bo0 = bo[0];
    #pragma unroll
    for (int mt = 0; mt < 2; mt++) {
        #pragma unroll
        for (int rr = 0; rr < 2; rr++) {
            int row_local = wm*32 + mt*16 + rr*8 + g;
            int b = (base + row_local) & (BB - 1);
            const float* hqb = g_hq2 + b*HH;
            float part = 0.f;
            #pragma unroll
            for (int nt = 0; nt < 8; nt++) {
                int h0 = wn*64 + nt*8 + t*2;
                float x0 = acc[mt][nt][rr*2+0] + __ldg(hqb + h0);
                float x1 = acc[mt][nt][rr*2+1] + __ldg(hqb + h0 + 1);
                part += wos[h0] * tanhf(x0) + wos[h0+1] * tanhf(x1);
            }
            part += __shfl_xor_sync(0xffffffffu, part, 1);
            part += __shfl_xor_sync(0xffffffffu, part, 2);
            if (t == 0) red[row_local*4 + wn] = part;
        }
    }
    __syncthreads();
    if (tid < 128)
        g_logit[base + tid] = red[tid*4+0] + red[tid*4+1] + red[tid*4+2] + red[tid*4+3] + bo0;
}

// ---------------------------------------------------------------------------
// Kernel 3: softmax per batch over S; writes final p[b*S+s] into the output.
// ---------------------------------------------------------------------------
__global__ void softmax_kernel(float* __restrict__ p) {
    int b = blockIdx.x, t = threadIdx.x;   // 256 threads
    __shared__ float red[256];
    float m = -3.4e38f;
    for (int s = t; s < SS; s += 256) m = fmaxf(m, g_logit[s*BB + b]);
    red[t] = m; __syncthreads();
    for (int off = 128; off; off >>= 1) {
        if (t < off) red[t] = fmaxf(red[t], red[t + off]);
        __syncthreads();
    }
    m = red[0]; __syncthreads();

    float sum = 0.f;
    for (int s = t; s < SS; s += 256) {
        float e = expf(g_logit[s*BB + b] - m);
        p[b*SS + s] = e;
        sum += e;
    }
    red[t] = sum; __syncthreads();
    for (int off = 128; off; off >>= 1) {
        if (t < off) red[t] += red[t + off];
        __syncthreads();
    }
    float rinv = 1.f / red[0];
    for (int s = t; s < SS; s += 256) p[b*SS + s] *= rinv;
}

// ---------------------------------------------------------------------------
// Kernel 4: partial weighted sum over an s-chunk (float4, smem-staged p):
//   g_partial[sc][b][vc] = sum_{s in chunk} p[b][s] * v[s][b][vc]
// ---------------------------------------------------------------------------
__global__ void wsum_kernel(const float* __restrict__ v, const float* __restrict__ p) {
    int b  = blockIdx.x;
    int sc = blockIdx.y;
    int vc4 = threadIdx.x;   // 128 threads, one float4 each (covers V=512)
    __shared__ float ps[SPER];
    if (threadIdx.x < SPER) ps[threadIdx.x] = p[b*SS + sc*SPER + threadIdx.x];
    __syncthreads();

    const float4* vp = (const float4*)(v + ((size_t)(sc*SPER)*BB + b) * VV) + vc4;
    const size_t stride4 = (size_t)BB * VV / 4;  // float4 stride over s
    float4 acc = make_float4(0.f, 0.f, 0.f, 0.f);
    #pragma unroll 8
    for (int s = 0; s < SPER; s++) {
        float  w = ps[s];
        float4 tv = vp[(size_t)s * stride4];
        acc.x += w * tv.x; acc.y += w * tv.y;
        acc.z += w * tv.z; acc.w += w * tv.w;
    }
    ((float4*)(g_partial + ((size_t)(sc*BB + b)) * VV))[vc4] = acc;
}

// ---------------------------------------------------------------------------
// Kernel 5: reduce split-S partials -> out[b*V + vc]  (deterministic)
// ---------------------------------------------------------------------------
__global__ void reduce_kernel(float* __restrict__ out) {
    int idx = blockIdx.x * 256 + threadIdx.x;  // 16384 total
    float acc = 0.f;
    #pragma unroll
    for (int c = 0; c < SCH; c++) acc += g_partial[c*BB*VV + idx];
    out[idx] = acc;
}

// ---------------------------------------------------------------------------
extern "C" void kernel_launch(void* const* d_in, const int* in_sizes, int n_in,
                              void* d_out, int out_size) {
    const float* q  = (const float*)d_in[0];
    const float* k  = (const float*)d_in[1];
    const float* v  = (const float*)d_in[2];
    const float* Wk = (const float*)d_in[3];
    const float* bk = (const float*)d_in[4];
    const float* Wq = (const float*)d_in[5];
    const float* bq = (const float*)d_in[6];
    const float* Wo = (const float*)d_in[7];
    const float* bo = (const float*)d_in[8];

    float* out = (float*)d_out;          // [1, B, V] -> B*V floats
    float* p   = out + BB*VV;            // [B, S]    -> B*S floats

    static int smem_set = 0;
    if (!smem_set) {
        cudaFuncSetAttribute(logit_kernel,
                             cudaFuncAttributeMaxDynamicSharedMemorySize, LOGIT_SMEM);
        smem_set = 1;
    }

    hq_kernel<<<BB, HH>>>(q, Wq, bq, bk);
    logit_kernel<<<MT/128, 512, LOGIT_SMEM>>>(k, Wk, Wo, bo);
    softmax_kernel<<<BB, 256>>>(p);
    dim3 g4(BB, SCH);
    wsum_kernel<<<g4, 128>>>(v, p);
    reduce_kernel<<<BB*VV/256, 256>>>(out);
}